// round 1
// baseline (speedup 1.0000x reference)
#include <cuda_runtime.h>
#include <cuda_bf16.h>
#include <cstdint>

// Problem dims (fixed by the dataset)
#define S_   128
#define N_   384
#define CM_  256
#define CH_  32
#define CZ_  128
#define P_   (N_*CH_)       // 12288
#define R_   (S_*N_)        // 49152

// Scratch (device globals — no allocation allowed)
__device__ __align__(128) float g_a2[S_*P_];          // a2[s][n*32+c]
__device__ __align__(128) float g_b2[S_*P_];          // b2[s][n*32+d]
__device__ __align__(128) float g_C1[(size_t)P_*P_];  // outer, 604MB fp32
__device__ __align__(16)  float2 g_stats[R_];         // (mu, rstd) per row
__device__ __align__(16)  float g_norm[N_*N_];        // mask norm + eps

__device__ __forceinline__ uint32_t f2tf(float f){
    uint32_t u; asm("cvt.rna.tf32.f32 %0, %1;" : "=r"(u) : "f"(f)); return u;
}

__device__ __forceinline__ void mma8(float d[4], const uint32_t a[4], const uint32_t b[2], const float c[4]){
    asm volatile(
      "mma.sync.aligned.m16n8k8.row.col.f32.tf32.tf32.f32 "
      "{%0,%1,%2,%3},{%4,%5,%6,%7},{%8,%9},{%10,%11,%12,%13};\n"
      : "=f"(d[0]),"=f"(d[1]),"=f"(d[2]),"=f"(d[3])
      : "r"(a[0]),"r"(a[1]),"r"(a[2]),"r"(a[3]),
        "r"(b[0]),"r"(b[1]),
        "f"(c[0]),"f"(c[1]),"f"(c[2]),"f"(c[3]));
}

// ---------------------------------------------------------------------------
// K1a: per-row LayerNorm statistics
// ---------------------------------------------------------------------------
__global__ void k_stats(const float* __restrict__ m){
    int r = blockIdx.x*8 + (threadIdx.x>>5);
    int lane = threadIdx.x & 31;
    const float* row = m + (size_t)r*CM_;
    float s=0.f, s2=0.f;
#pragma unroll
    for (int j=0;j<8;j++){ float x = row[j*32+lane]; s += x; s2 += x*x; }
#pragma unroll
    for (int o=16;o;o>>=1){ s += __shfl_xor_sync(~0u,s,o); s2 += __shfl_xor_sync(~0u,s2,o); }
    if (lane==0){
        float mu = s*(1.f/CM_);
        float var = s2*(1.f/CM_) - mu*mu;
        g_stats[r] = make_float2(mu, rsqrtf(var + 1e-5f));
    }
}

// ---------------------------------------------------------------------------
// K0: norm[i,j] = sum_s mask[s,i]*mask[s,j] + 1e-3
// ---------------------------------------------------------------------------
__global__ void k_norm(const float* __restrict__ mask){
    __shared__ float mi[S_];
    int i = blockIdx.x, j = threadIdx.x;
    if (j < S_) mi[j] = mask[(size_t)j*N_ + i];
    __syncthreads();
    float acc = 0.f;
#pragma unroll 4
    for (int s=0;s<S_;s++) acc += mi[s]*mask[(size_t)s*N_ + j];
    g_norm[i*N_ + j] = acc + 1e-3f;
}

// ---------------------------------------------------------------------------
// K1b: fused LN-normalize + dual projection GEMM
//      A[r,k] = (m[r,k]-mu)*rstd*gamma[k]+beta[k], W = [w1 | w2]  (K=256, N=64)
//      writes a2[s][n*32+h], b2[s][n*32+h]  (masked, biased)
// ---------------------------------------------------------------------------
__global__ __launch_bounds__(256) void k_proj(
    const float* __restrict__ m, const float* __restrict__ mask,
    const float* __restrict__ gamma, const float* __restrict__ beta,
    const float* __restrict__ w1, const float* __restrict__ b1,
    const float* __restrict__ w2, const float* __restrict__ b2)
{
    __shared__ float As[128][36];   // [row][k]
    __shared__ float Bs[32][72];    // [k][h]
    int r0 = blockIdx.x*128;
    int t = threadIdx.x, wid = t>>5, lane = t&31;
    int g = lane>>2, tig = lane&3;
    int wm = (wid&1)*64, wn = (wid>>1)*16;
    float acc[4][2][4] = {};

    for (int k0=0;k0<CM_;k0+=32){
        // load + normalize A chunk: 128 rows x 32 k
#pragma unroll
        for (int q=0;q<4;q++){
            int f = t + q*256;          // float4 index, 0..1023
            int row = f>>3; int k4 = (f&7)*4;
            float4 x  = *(const float4*)(m + (size_t)(r0+row)*CM_ + k0 + k4);
            float2 st = g_stats[r0+row];
            float4 gm = *(const float4*)(gamma + k0 + k4);
            float4 bt = *(const float4*)(beta  + k0 + k4);
            float4 v;
            v.x = (x.x-st.x)*st.y*gm.x + bt.x;
            v.y = (x.y-st.x)*st.y*gm.y + bt.y;
            v.z = (x.z-st.x)*st.y*gm.z + bt.z;
            v.w = (x.w-st.x)*st.y*gm.w + bt.w;
            *(float4*)&As[row][k4] = v;
        }
        // load W chunk: 32 k x 64 h  (w1 cols 0..31, w2 cols 32..63)
#pragma unroll
        for (int q=0;q<2;q++){
            int f = t + q*256;          // 0..511 float4
            int k_l = f>>4; int h4 = (f&15)*4;
            float4 w;
            if (h4 < 32) w = *(const float4*)(w1 + (size_t)(k0+k_l)*CH_ + h4);
            else         w = *(const float4*)(w2 + (size_t)(k0+k_l)*CH_ + (h4-32));
            *(float4*)&Bs[k_l][h4] = w;
        }
        __syncthreads();
#pragma unroll
        for (int kk=0;kk<32;kk+=8){
            uint32_t af[4][4], bfr[2][2];
#pragma unroll
            for (int mi=0;mi<4;mi++){
                int mb = wm + mi*16;
                af[mi][0]=f2tf(As[mb+g  ][kk+tig  ]);
                af[mi][1]=f2tf(As[mb+g+8][kk+tig  ]);
                af[mi][2]=f2tf(As[mb+g  ][kk+tig+4]);
                af[mi][3]=f2tf(As[mb+g+8][kk+tig+4]);
            }
#pragma unroll
            for (int ni=0;ni<2;ni++){
                int nb = wn + ni*8;
                bfr[ni][0]=f2tf(Bs[kk+tig  ][nb+g]);
                bfr[ni][1]=f2tf(Bs[kk+tig+4][nb+g]);
            }
#pragma unroll
            for (int mi=0;mi<4;mi++)
#pragma unroll
                for (int ni=0;ni<2;ni++)
                    mma8(acc[mi][ni], af[mi], bfr[ni], acc[mi][ni]);
        }
        __syncthreads();
    }
    // epilogue: bias, mask, scatter to a2/b2
#pragma unroll
    for (int mi=0;mi<4;mi++){
#pragma unroll
        for (int ni=0;ni<2;ni++){
            int h0 = wn + ni*8 + tig*2;
#pragma unroll
            for (int half=0; half<2; half++){
                int r = r0 + wm + mi*16 + g + half*8;
                int s_ = r / N_;
                int n_ = r - s_*N_;
                float mv = mask[(size_t)s_*N_ + n_];
#pragma unroll
                for (int e=0;e<2;e++){
                    int h = h0 + e;
                    float v = acc[mi][ni][half*2+e];
                    if (h < CH_) g_a2[(size_t)s_*P_ + n_*CH_ + h]        = (v + __ldg(&b1[h]))*mv;
                    else         g_b2[(size_t)s_*P_ + n_*CH_ + (h-CH_)]  = (v + __ldg(&b2[h-CH_]))*mv;
                }
            }
        }
    }
}

// ---------------------------------------------------------------------------
// K2: outer GEMM  C1[p,q] = sum_s a2[s][p]*b2[s][q]   (12288x12288, K=128)
// ---------------------------------------------------------------------------
__global__ __launch_bounds__(256,2) void k_outer(){
    __shared__ float As[32][136];   // [k][p]
    __shared__ float Bs[32][136];   // [k][q]
    int p0 = blockIdx.x*128, q0 = blockIdx.y*128;
    int t = threadIdx.x, wid = t>>5, lane = t&31;
    int g = lane>>2, tig = lane&3;
    int wm = (wid&1)*64, wn = (wid>>1)*32;
    float acc[4][4][4] = {};

    for (int kc=0;kc<S_;kc+=32){
#pragma unroll
        for (int q=0;q<4;q++){
            int f = t + q*256;          // 0..1023 float4
            int s_l = f>>5; int p4 = (f&31)*4;
            *(float4*)&As[s_l][p4] = *(const float4*)(g_a2 + (size_t)(kc+s_l)*P_ + p0 + p4);
            *(float4*)&Bs[s_l][p4] = *(const float4*)(g_b2 + (size_t)(kc+s_l)*P_ + q0 + p4);
        }
        __syncthreads();
#pragma unroll
        for (int kk=0;kk<32;kk+=8){
            uint32_t af[4][4], bfr[4][2];
#pragma unroll
            for (int mi=0;mi<4;mi++){
                int mb = wm + mi*16;
                af[mi][0]=f2tf(As[kk+tig  ][mb+g  ]);
                af[mi][1]=f2tf(As[kk+tig  ][mb+g+8]);
                af[mi][2]=f2tf(As[kk+tig+4][mb+g  ]);
                af[mi][3]=f2tf(As[kk+tig+4][mb+g+8]);
            }
#pragma unroll
            for (int ni=0;ni<4;ni++){
                int nb = wn + ni*8;
                bfr[ni][0]=f2tf(Bs[kk+tig  ][nb+g]);
                bfr[ni][1]=f2tf(Bs[kk+tig+4][nb+g]);
            }
#pragma unroll
            for (int mi=0;mi<4;mi++)
#pragma unroll
                for (int ni=0;ni<4;ni++)
                    mma8(acc[mi][ni], af[mi], bfr[ni], acc[mi][ni]);
        }
        __syncthreads();
    }
#pragma unroll
    for (int mi=0;mi<4;mi++){
#pragma unroll
        for (int ni=0;ni<4;ni++){
            size_t row = (size_t)(p0 + wm + mi*16 + g);
            int col = q0 + wn + ni*8 + tig*2;
            float2 v0 = make_float2(acc[mi][ni][0], acc[mi][ni][1]);
            float2 v1 = make_float2(acc[mi][ni][2], acc[mi][ni][3]);
            *(float2*)&g_C1[row*P_ + col]     = v0;
            *(float2*)&g_C1[(row+8)*P_ + col] = v1;
        }
    }
}

// ---------------------------------------------------------------------------
// K3: out[(i,j),z] = (sum_{c,d} C1[i*32+c, j*32+d] * w_out[c*32+d, z] + b_out[z]) / norm[i,j]
//      grid: (3 j-tiles, 384 i), BM=128 pairs, BN=128 z, K=1024 in 32-chunks
// ---------------------------------------------------------------------------
__global__ __launch_bounds__(256,2) void k_out(
    const float* __restrict__ Wout, const float* __restrict__ bout,
    float* __restrict__ out)
{
    __shared__ float As[128][36];   // [j_local][d]
    __shared__ float Bs[32][136];   // [k][z]
    int i  = blockIdx.y;
    int j0 = blockIdx.x*128;
    int t = threadIdx.x, wid = t>>5, lane = t&31;
    int g = lane>>2, tig = lane&3;
    int wm = (wid&1)*64, wn = (wid>>1)*32;
    float acc[4][4][4] = {};

    for (int c=0;c<CH_;c++){
        const float* arow = g_C1 + (size_t)(i*CH_ + c)*P_ + (size_t)j0*CH_;
#pragma unroll
        for (int q=0;q<4;q++){
            int f = t + q*256;          // 0..1023 float4 (contiguous 16KB slab)
            float4 v = *(const float4*)(arow + (size_t)f*4);
            int row = f>>3; int d4 = (f&7)*4;
            *(float4*)&As[row][d4] = v;
        }
#pragma unroll
        for (int q=0;q<4;q++){
            int f = t + q*256;
            int k_l = f>>5; int z4 = (f&31)*4;
            *(float4*)&Bs[k_l][z4] = *(const float4*)(Wout + (size_t)(c*CH_ + k_l)*CZ_ + z4);
        }
        __syncthreads();
#pragma unroll
        for (int kk=0;kk<32;kk+=8){
            uint32_t af[4][4], bfr[4][2];
#pragma unroll
            for (int mi=0;mi<4;mi++){
                int mb = wm + mi*16;
                af[mi][0]=f2tf(As[mb+g  ][kk+tig  ]);
                af[mi][1]=f2tf(As[mb+g+8][kk+tig  ]);
                af[mi][2]=f2tf(As[mb+g  ][kk+tig+4]);
                af[mi][3]=f2tf(As[mb+g+8][kk+tig+4]);
            }
#pragma unroll
            for (int ni=0;ni<4;ni++){
                int nb = wn + ni*8;
                bfr[ni][0]=f2tf(Bs[kk+tig  ][nb+g]);
                bfr[ni][1]=f2tf(Bs[kk+tig+4][nb+g]);
            }
#pragma unroll
            for (int mi=0;mi<4;mi++)
#pragma unroll
                for (int ni=0;ni<4;ni++)
                    mma8(acc[mi][ni], af[mi], bfr[ni], acc[mi][ni]);
        }
        __syncthreads();
    }
#pragma unroll
    for (int mi=0;mi<4;mi++){
#pragma unroll
        for (int ni=0;ni<4;ni++){
            int z = wn + ni*8 + tig*2;
            float bo0 = __ldg(&bout[z]), bo1 = __ldg(&bout[z+1]);
#pragma unroll
            for (int half=0; half<2; half++){
                int jl = wm + mi*16 + g + half*8;
                float inv = 1.f / g_norm[i*N_ + j0 + jl];
                float2 v = make_float2((acc[mi][ni][half*2+0] + bo0)*inv,
                                       (acc[mi][ni][half*2+1] + bo1)*inv);
                *(float2*)&out[((size_t)(i*N_ + j0 + jl))*CZ_ + z] = v;
            }
        }
    }
}

// ---------------------------------------------------------------------------
extern "C" void kernel_launch(void* const* d_in, const int* in_sizes, int n_in,
                              void* d_out, int out_size)
{
    const float* m     = (const float*)d_in[0];
    const float* mask  = (const float*)d_in[1];
    const float* gamma = (const float*)d_in[2];
    const float* beta  = (const float*)d_in[3];
    const float* w1    = (const float*)d_in[4];
    const float* b1    = (const float*)d_in[5];
    const float* w2    = (const float*)d_in[6];
    const float* b2    = (const float*)d_in[7];
    const float* w_out = (const float*)d_in[8];
    const float* b_out = (const float*)d_in[9];
    float* out = (float*)d_out;

    k_stats<<<R_/8, 256>>>(m);
    k_norm<<<N_, N_>>>(mask);
    k_proj<<<R_/128, 256>>>(m, mask, gamma, beta, w1, b1, w2, b2);
    dim3 g2(P_/128, P_/128);
    k_outer<<<g2, 256>>>();
    dim3 g3(N_/128, N_);
    k_out<<<g3, 256>>>(w_out, b_out, out);
}

// round 4
// speedup vs baseline: 1.9075x; 1.9075x over previous
#include <cuda_runtime.h>
#include <cuda_fp16.h>
#include <cstdint>

#define S_   128
#define N_   384
#define CM_  256
#define CH_  32
#define CZ_  128
#define P_   (N_*CH_)       // 12288
#define R_   (S_*N_)        // 49152

// Scratch (device globals)
__device__ __align__(128) float  g_a2 [S_*P_];           // [s][p] fp32
__device__ __align__(128) float  g_b2 [S_*P_];
__device__ __align__(128) __half g_a2T[(size_t)P_*S_];   // [p][s] fp16
__device__ __align__(128) __half g_b2T[(size_t)P_*S_];
__device__ __align__(128) __half g_C1h[(size_t)P_*P_];   // outer product fp16 (302MB)
__device__ __align__(128) __half g_w16T[32*128*32];      // [c][z][d] fp16
__device__ __align__(16)  float2 g_stats[R_];
__device__ __align__(16)  float  g_norm[N_*N_];

// ---------------- helpers ----------------
__device__ __forceinline__ uint32_t f2tf(float f){
    uint32_t u; asm("cvt.rna.tf32.f32 %0, %1;" : "=r"(u) : "f"(f)); return u;
}
__device__ __forceinline__ uint32_t cvta_smem(const void* p){
    uint32_t a; asm("{ .reg .u64 t; cvta.to.shared.u64 t, %1; cvt.u32.u64 %0, t; }" : "=r"(a) : "l"(p)); return a;
}
__device__ __forceinline__ void ldmx4(uint32_t& r0, uint32_t& r1, uint32_t& r2, uint32_t& r3, uint32_t addr){
    asm volatile("ldmatrix.sync.aligned.m8n8.x4.shared.b16 {%0,%1,%2,%3}, [%4];"
        : "=r"(r0), "=r"(r1), "=r"(r2), "=r"(r3) : "r"(addr));
}
__device__ __forceinline__ void mma8(float d[4], const uint32_t a[4], const uint32_t b[2], const float c[4]){
    asm volatile(
      "mma.sync.aligned.m16n8k8.row.col.f32.tf32.tf32.f32 "
      "{%0,%1,%2,%3},{%4,%5,%6,%7},{%8,%9},{%10,%11,%12,%13};\n"
      : "=f"(d[0]),"=f"(d[1]),"=f"(d[2]),"=f"(d[3])
      : "r"(a[0]),"r"(a[1]),"r"(a[2]),"r"(a[3]),
        "r"(b[0]),"r"(b[1]),
        "f"(c[0]),"f"(c[1]),"f"(c[2]),"f"(c[3]));
}
__device__ __forceinline__ void hmma16(float d[4], const uint32_t a[4], const uint32_t b[2]){
    asm volatile(
      "mma.sync.aligned.m16n8k16.row.col.f32.f16.f16.f32 "
      "{%0,%1,%2,%3},{%4,%5,%6,%7},{%8,%9},{%0,%1,%2,%3};\n"
      : "+f"(d[0]),"+f"(d[1]),"+f"(d[2]),"+f"(d[3])
      : "r"(a[0]),"r"(a[1]),"r"(a[2]),"r"(a[3]),
        "r"(b[0]),"r"(b[1]));
}

// ---------------------------------------------------------------------------
// K1a: per-row LayerNorm statistics
// ---------------------------------------------------------------------------
__global__ void k_stats(const float* __restrict__ m){
    int r = blockIdx.x*8 + (threadIdx.x>>5);
    int lane = threadIdx.x & 31;
    const float* row = m + (size_t)r*CM_;
    float s=0.f, s2=0.f;
#pragma unroll
    for (int j=0;j<8;j++){ float x = row[j*32+lane]; s += x; s2 += x*x; }
#pragma unroll
    for (int o=16;o;o>>=1){ s += __shfl_xor_sync(~0u,s,o); s2 += __shfl_xor_sync(~0u,s2,o); }
    if (lane==0){
        float mu = s*(1.f/CM_);
        float var = s2*(1.f/CM_) - mu*mu;
        g_stats[r] = make_float2(mu, rsqrtf(var + 1e-5f));
    }
}

// ---------------------------------------------------------------------------
// K0: norm[i,j]
// ---------------------------------------------------------------------------
__global__ void k_norm(const float* __restrict__ mask){
    __shared__ float mi[S_];
    int i = blockIdx.x, j = threadIdx.x;
    if (j < S_) mi[j] = mask[(size_t)j*N_ + i];
    __syncthreads();
    float acc = 0.f;
#pragma unroll 4
    for (int s=0;s<S_;s++) acc += mi[s]*mask[(size_t)s*N_ + j];
    g_norm[i*N_ + j] = acc + 1e-3f;
}

// ---------------------------------------------------------------------------
// K_w: w_out -> fp16, transposed per c-chunk: g_w16T[c][z][d]
// ---------------------------------------------------------------------------
__global__ void k_cvtw(const float* __restrict__ w_out){
    int o = blockIdx.x*256 + threadIdx.x;        // [c][z][d]
    int d = o & 31, z = (o>>5) & 127, c = o>>12;
    g_w16T[o] = __float2half(w_out[(size_t)(c*32+d)*CZ_ + z]);
}

// ---------------------------------------------------------------------------
// K1b: fused LN + dual projection (legacy tf32 mma)
// ---------------------------------------------------------------------------
__global__ __launch_bounds__(256) void k_proj(
    const float* __restrict__ m, const float* __restrict__ mask,
    const float* __restrict__ gamma, const float* __restrict__ beta,
    const float* __restrict__ w1, const float* __restrict__ b1,
    const float* __restrict__ w2, const float* __restrict__ b2)
{
    __shared__ float As[128][36];
    __shared__ float Bs[32][72];
    int r0 = blockIdx.x*128;
    int t = threadIdx.x, wid = t>>5, lane = t&31;
    int g = lane>>2, tig = lane&3;
    int wm = (wid&1)*64, wn = (wid>>1)*16;
    float acc[4][2][4] = {};

    for (int k0=0;k0<CM_;k0+=32){
#pragma unroll
        for (int q=0;q<4;q++){
            int f = t + q*256;
            int row = f>>3; int k4 = (f&7)*4;
            float4 x  = *(const float4*)(m + (size_t)(r0+row)*CM_ + k0 + k4);
            float2 st = g_stats[r0+row];
            float4 gm = *(const float4*)(gamma + k0 + k4);
            float4 bt = *(const float4*)(beta  + k0 + k4);
            float4 v;
            v.x = (x.x-st.x)*st.y*gm.x + bt.x;
            v.y = (x.y-st.x)*st.y*gm.y + bt.y;
            v.z = (x.z-st.x)*st.y*gm.z + bt.z;
            v.w = (x.w-st.x)*st.y*gm.w + bt.w;
            *(float4*)&As[row][k4] = v;
        }
#pragma unroll
        for (int q=0;q<2;q++){
            int f = t + q*256;
            int k_l = f>>4; int h4 = (f&15)*4;
            float4 w;
            if (h4 < 32) w = *(const float4*)(w1 + (size_t)(k0+k_l)*CH_ + h4);
            else         w = *(const float4*)(w2 + (size_t)(k0+k_l)*CH_ + (h4-32));
            *(float4*)&Bs[k_l][h4] = w;
        }
        __syncthreads();
#pragma unroll
        for (int kk=0;kk<32;kk+=8){
            uint32_t af[4][4], bfr[2][2];
#pragma unroll
            for (int mi=0;mi<4;mi++){
                int mb = wm + mi*16;
                af[mi][0]=f2tf(As[mb+g  ][kk+tig  ]);
                af[mi][1]=f2tf(As[mb+g+8][kk+tig  ]);
                af[mi][2]=f2tf(As[mb+g  ][kk+tig+4]);
                af[mi][3]=f2tf(As[mb+g+8][kk+tig+4]);
            }
#pragma unroll
            for (int ni=0;ni<2;ni++){
                int nb = wn + ni*8;
                bfr[ni][0]=f2tf(Bs[kk+tig  ][nb+g]);
                bfr[ni][1]=f2tf(Bs[kk+tig+4][nb+g]);
            }
#pragma unroll
            for (int mi=0;mi<4;mi++)
#pragma unroll
                for (int ni=0;ni<2;ni++)
                    mma8(acc[mi][ni], af[mi], bfr[ni], acc[mi][ni]);
        }
        __syncthreads();
    }
#pragma unroll
    for (int mi=0;mi<4;mi++){
#pragma unroll
        for (int ni=0;ni<2;ni++){
            int h0 = wn + ni*8 + tig*2;
#pragma unroll
            for (int half=0; half<2; half++){
                int r = r0 + wm + mi*16 + g + half*8;
                int s_ = r / N_;
                int n_ = r - s_*N_;
                float mv = mask[(size_t)s_*N_ + n_];
#pragma unroll
                for (int e=0;e<2;e++){
                    int h = h0 + e;
                    float v = acc[mi][ni][half*2+e];
                    if (h < CH_) g_a2[(size_t)s_*P_ + n_*CH_ + h]       = (v + __ldg(&b1[h]))*mv;
                    else         g_b2[(size_t)s_*P_ + n_*CH_ + (h-CH_)] = (v + __ldg(&b2[h-CH_]))*mv;
                }
            }
        }
    }
}

// ---------------------------------------------------------------------------
// K_tr: transpose a2/b2 [S][P] fp32 -> [P][S] fp16
// ---------------------------------------------------------------------------
__global__ void k_tr(){
    __shared__ float tl[32][33];
    const float* src = blockIdx.z ? g_b2 : g_a2;
    __half*      dst = blockIdx.z ? g_b2T : g_a2T;
    int x = blockIdx.x*32 + threadIdx.x;
    int y0 = blockIdx.y*32;
#pragma unroll
    for (int i=0;i<4;i++)
        tl[threadIdx.y + i*8][threadIdx.x] = src[(size_t)(y0+threadIdx.y+i*8)*P_ + x];
    __syncthreads();
#pragma unroll
    for (int i=0;i<4;i++)
        dst[(size_t)(blockIdx.x*32 + threadIdx.y + i*8)*S_ + y0 + threadIdx.x]
            = __float2half(tl[threadIdx.x][threadIdx.y + i*8]);
}

// ---------------------------------------------------------------------------
// K2: fp16 outer GEMM. C1[p,q] = sum_s a2T[p][s]*b2T[q][s].
//     BM=BN=128, K=128 fully resident. ldmatrix.x4 + mma.m16n8k16.
// ---------------------------------------------------------------------------
#define OSTR 136  // smem row stride in halves (128 + 8 pad)
__global__ __launch_bounds__(256,2) void k_outer_h(){
    extern __shared__ __align__(16) __half sm[];
    __half* Ah = sm;               // 128 x OSTR
    __half* Bh = sm + 128*OSTR;    // 128 x OSTR
    int t = threadIdx.x, wid = t>>5, lane = t&31;
    int g = lane>>2, tig = lane&3;
    int p0 = blockIdx.x*128, q0 = blockIdx.y*128;
    int wm = (wid&1)*64, wn = (wid>>1)*32;

    // load tiles (each row = 128 halves = 16 uint4)
#pragma unroll
    for (int q=0;q<8;q++){
        int idx = t + q*256;
        int row = idx>>4, u = idx&15;
        *(uint4*)&Ah[row*OSTR + u*8] = *(const uint4*)(g_a2T + (size_t)(p0+row)*S_ + u*8);
        *(uint4*)&Bh[row*OSTR + u*8] = *(const uint4*)(g_b2T + (size_t)(q0+row)*S_ + u*8);
    }
    __syncthreads();

    uint32_t a_base = cvta_smem(Ah);
    uint32_t b_base = cvta_smem(Bh);
    float acc[4][4][4] = {};
    int lrow = lane & 15, lcol = (lane>>4)*8;

#pragma unroll
    for (int kk=0;kk<8;kk++){
        int k0 = kk*16;
        uint32_t af[4][4], bf[4][2];
#pragma unroll
        for (int mi=0;mi<4;mi++){
            uint32_t addr = a_base + (uint32_t)(((wm + mi*16 + lrow)*OSTR + k0 + lcol)*2);
            ldmx4(af[mi][0], af[mi][1], af[mi][2], af[mi][3], addr);
        }
#pragma unroll
        for (int np=0;np<2;np++){
            uint32_t addr = b_base + (uint32_t)(((wn + np*16 + lrow)*OSTR + k0 + lcol)*2);
            uint32_t r0,r1,r2,r3;
            ldmx4(r0,r1,r2,r3,addr);
            bf[np*2  ][0]=r0; bf[np*2  ][1]=r2;
            bf[np*2+1][0]=r1; bf[np*2+1][1]=r3;
        }
#pragma unroll
        for (int mi=0;mi<4;mi++)
#pragma unroll
            for (int ni=0;ni<4;ni++)
                hmma16(acc[mi][ni], af[mi], bf[ni]);
    }
    __syncthreads();

    // stage fp16 result in smem, then coalesced global store
    __half* Cs = Ah;
#pragma unroll
    for (int mi=0;mi<4;mi++)
#pragma unroll
        for (int ni=0;ni<4;ni++){
            int col = wn + ni*8 + tig*2;
#pragma unroll
            for (int half=0; half<2; half++){
                int row = wm + mi*16 + g + half*8;
                __half2 h = __floats2half2_rn(acc[mi][ni][half*2+0], acc[mi][ni][half*2+1]);
                *(__half2*)&Cs[row*OSTR + col] = h;
            }
        }
    __syncthreads();
#pragma unroll
    for (int q=0;q<8;q++){
        int idx = t + q*256;
        int row = idx>>4, u = idx&15;
        *(uint4*)(g_C1h + (size_t)(p0+row)*P_ + q0 + u*8) = *(uint4*)&Cs[row*OSTR + u*8];
    }
}

// ---------------------------------------------------------------------------
// K3: fp16 mma. out[(i,j),z] over K=(c,d)=1024 in 32 chunks of 32.
// ---------------------------------------------------------------------------
__global__ __launch_bounds__(256,2) void k_out16(const float* __restrict__ bout,
                                                 float* __restrict__ out)
{
    __shared__ __half As[2][128*40];
    __shared__ __half Ws[2][128*40];
    int i  = blockIdx.y;
    int j0 = blockIdx.x*128;
    int t = threadIdx.x, wid = t>>5, lane = t&31;
    int g = lane>>2, tig = lane&3;
    int wm = (wid&1)*64, wn = (wid>>1)*32;
    float acc[4][4][4] = {};

    uint4 ra[2], rw[2];
    const uint4* asrc0 = (const uint4*)(g_C1h + (size_t)(i*CH_)*P_ + (size_t)j0*CH_);
    const uint4* wsrc0 = (const uint4*)g_w16T;
#pragma unroll
    for (int q=0;q<2;q++){
        int idx = t + q*256;
        ra[q] = asrc0[idx];
        rw[q] = wsrc0[idx];
    }
#pragma unroll
    for (int q=0;q<2;q++){
        int idx = t + q*256;
        int r_ = idx>>2, s_ = idx&3;
        *(uint4*)&As[0][r_*40 + s_*8] = ra[q];
        *(uint4*)&Ws[0][r_*40 + s_*8] = rw[q];
    }
    __syncthreads();

    for (int c=0;c<32;c++){
        int b = c&1;
        if (c<31){
            const uint4* asrc = (const uint4*)(g_C1h + (size_t)(i*CH_+c+1)*P_ + (size_t)j0*CH_);
            const uint4* wsrc = (const uint4*)(g_w16T + (size_t)(c+1)*4096);
#pragma unroll
            for (int q=0;q<2;q++){
                int idx = t + q*256;
                ra[q] = asrc[idx];
                rw[q] = wsrc[idx];
            }
        }
#pragma unroll
        for (int kk=0;kk<2;kk++){
            uint32_t af[4][4], bf[4][2];
#pragma unroll
            for (int mi=0;mi<4;mi++){
                int j = wm + mi*16 + g;
                const __half* base = &As[b][j*40 + kk*16 + tig*2];
                af[mi][0] = *(const uint32_t*)(base);
                af[mi][1] = *(const uint32_t*)(base + 8*40);
                af[mi][2] = *(const uint32_t*)(base + 8);
                af[mi][3] = *(const uint32_t*)(base + 8*40 + 8);
            }
#pragma unroll
            for (int ni=0;ni<4;ni++){
                int z = wn + ni*8 + g;
                const __half* base = &Ws[b][z*40 + kk*16 + tig*2];
                bf[ni][0] = *(const uint32_t*)(base);
                bf[ni][1] = *(const uint32_t*)(base + 8);
            }
#pragma unroll
            for (int mi=0;mi<4;mi++)
#pragma unroll
                for (int ni=0;ni<4;ni++)
                    hmma16(acc[mi][ni], af[mi], bf[ni]);
        }
        __syncthreads();
        if (c<31){
#pragma unroll
            for (int q=0;q<2;q++){
                int idx = t + q*256;
                int r_ = idx>>2, s_ = idx&3;
                *(uint4*)&As[b^1][r_*40 + s_*8] = ra[q];
                *(uint4*)&Ws[b^1][r_*40 + s_*8] = rw[q];
            }
            __syncthreads();
        }
    }
#pragma unroll
    for (int mi=0;mi<4;mi++){
#pragma unroll
        for (int ni=0;ni<4;ni++){
            int z = wn + ni*8 + tig*2;
            float bo0 = __ldg(&bout[z]), bo1 = __ldg(&bout[z+1]);
#pragma unroll
            for (int half=0; half<2; half++){
                int jl = wm + mi*16 + g + half*8;
                float inv = 1.f / g_norm[i*N_ + j0 + jl];
                float2 v = make_float2((acc[mi][ni][half*2+0] + bo0)*inv,
                                       (acc[mi][ni][half*2+1] + bo1)*inv);
                *(float2*)&out[((size_t)(i*N_ + j0 + jl))*CZ_ + z] = v;
            }
        }
    }
}

// ---------------------------------------------------------------------------
extern "C" void kernel_launch(void* const* d_in, const int* in_sizes, int n_in,
                              void* d_out, int out_size)
{
    const float* m     = (const float*)d_in[0];
    const float* mask  = (const float*)d_in[1];
    const float* gamma = (const float*)d_in[2];
    const float* beta  = (const float*)d_in[3];
    const float* w1    = (const float*)d_in[4];
    const float* b1    = (const float*)d_in[5];
    const float* w2    = (const float*)d_in[6];
    const float* b2    = (const float*)d_in[7];
    const float* w_out = (const float*)d_in[8];
    const float* b_out = (const float*)d_in[9];
    float* out = (float*)d_out;

    const int osmem = 2*128*OSTR*sizeof(__half);  // 69632
    cudaFuncSetAttribute(k_outer_h, cudaFuncAttributeMaxDynamicSharedMemorySize, osmem);

    k_stats<<<R_/8, 256>>>(m);
    k_norm<<<N_, N_>>>(mask);
    k_cvtw<<<(32*128*32)/256, 256>>>(w_out);
    k_proj<<<R_/128, 256>>>(m, mask, gamma, beta, w1, b1, w2, b2);
    dim3 gt(P_/32, S_/32, 2);
    k_tr<<<gt, dim3(32,8)>>>();
    dim3 g2(P_/128, P_/128);
    k_outer_h<<<g2, 256, osmem>>>();
    dim3 g3(N_/128, N_);
    k_out16<<<g3, 256>>>(b_out, out);
}

// round 5
// speedup vs baseline: 1.9483x; 1.0214x over previous
#include <cuda_runtime.h>
#include <cuda_fp16.h>
#include <cstdint>

#define S_   128
#define N_   384
#define CM_  256
#define CH_  32
#define CZ_  128
#define P_   (N_*CH_)       // 12288
#define R_   (S_*N_)        // 49152

// Scratch (device globals)
__device__ __align__(128) float  g_a2 [S_*P_];           // [s][p] fp32
__device__ __align__(128) float  g_b2 [S_*P_];
__device__ __align__(128) __half g_a2T[(size_t)P_*S_];   // [p][s] fp16
__device__ __align__(128) __half g_b2T[(size_t)P_*S_];
__device__ __align__(128) __half g_C1h[(size_t)P_*P_];   // outer product fp16 (302MB)
__device__ __align__(128) __half g_w16T[32*128*32];      // [c][z][d] fp16
__device__ __align__(16)  float2 g_stats[R_];
__device__ __align__(16)  float  g_norm[N_*N_];

// ---------------- helpers ----------------
__device__ __forceinline__ uint32_t f2tf(float f){
    uint32_t u; asm("cvt.rna.tf32.f32 %0, %1;" : "=r"(u) : "f"(f)); return u;
}
__device__ __forceinline__ uint32_t cvta_smem(const void* p){
    uint32_t a; asm("{ .reg .u64 t; cvta.to.shared.u64 t, %1; cvt.u32.u64 %0, t; }" : "=r"(a) : "l"(p)); return a;
}
__device__ __forceinline__ void ldmx4(uint32_t& r0, uint32_t& r1, uint32_t& r2, uint32_t& r3, uint32_t addr){
    asm volatile("ldmatrix.sync.aligned.m8n8.x4.shared.b16 {%0,%1,%2,%3}, [%4];"
        : "=r"(r0), "=r"(r1), "=r"(r2), "=r"(r3) : "r"(addr));
}
__device__ __forceinline__ void mma8(float d[4], const uint32_t a[4], const uint32_t b[2], const float c[4]){
    asm volatile(
      "mma.sync.aligned.m16n8k8.row.col.f32.tf32.tf32.f32 "
      "{%0,%1,%2,%3},{%4,%5,%6,%7},{%8,%9},{%10,%11,%12,%13};\n"
      : "=f"(d[0]),"=f"(d[1]),"=f"(d[2]),"=f"(d[3])
      : "r"(a[0]),"r"(a[1]),"r"(a[2]),"r"(a[3]),
        "r"(b[0]),"r"(b[1]),
        "f"(c[0]),"f"(c[1]),"f"(c[2]),"f"(c[3]));
}
__device__ __forceinline__ void hmma16(float d[4], const uint32_t a[4], const uint32_t b[2]){
    asm volatile(
      "mma.sync.aligned.m16n8k16.row.col.f32.f16.f16.f32 "
      "{%0,%1,%2,%3},{%4,%5,%6,%7},{%8,%9},{%0,%1,%2,%3};\n"
      : "+f"(d[0]),"+f"(d[1]),"+f"(d[2]),"+f"(d[3])
      : "r"(a[0]),"r"(a[1]),"r"(a[2]),"r"(a[3]),
        "r"(b[0]),"r"(b[1]));
}

// ---------------------------------------------------------------------------
// K1a: per-row LayerNorm statistics
// ---------------------------------------------------------------------------
__global__ void k_stats(const float* __restrict__ m){
    int r = blockIdx.x*8 + (threadIdx.x>>5);
    int lane = threadIdx.x & 31;
    const float* row = m + (size_t)r*CM_;
    float s=0.f, s2=0.f;
#pragma unroll
    for (int j=0;j<8;j++){ float x = row[j*32+lane]; s += x; s2 += x*x; }
#pragma unroll
    for (int o=16;o;o>>=1){ s += __shfl_xor_sync(~0u,s,o); s2 += __shfl_xor_sync(~0u,s2,o); }
    if (lane==0){
        float mu = s*(1.f/CM_);
        float var = s2*(1.f/CM_) - mu*mu;
        g_stats[r] = make_float2(mu, rsqrtf(var + 1e-5f));
    }
}

// ---------------------------------------------------------------------------
// K0: norm[i,j]
// ---------------------------------------------------------------------------
__global__ void k_norm(const float* __restrict__ mask){
    __shared__ float mi[S_];
    int i = blockIdx.x, j = threadIdx.x;
    if (j < S_) mi[j] = mask[(size_t)j*N_ + i];
    __syncthreads();
    float acc = 0.f;
#pragma unroll 4
    for (int s=0;s<S_;s++) acc += mi[s]*mask[(size_t)s*N_ + j];
    g_norm[i*N_ + j] = acc + 1e-3f;
}

// ---------------------------------------------------------------------------
// K_w: w_out -> fp16, transposed per c-chunk: g_w16T[c][z][d]
// ---------------------------------------------------------------------------
__global__ void k_cvtw(const float* __restrict__ w_out){
    int o = blockIdx.x*256 + threadIdx.x;        // [c][z][d]
    int d = o & 31, z = (o>>5) & 127, c = o>>12;
    g_w16T[o] = __float2half(w_out[(size_t)(c*32+d)*CZ_ + z]);
}

// ---------------------------------------------------------------------------
// K1b: fused LN + dual projection (legacy tf32 mma)
// ---------------------------------------------------------------------------
__global__ __launch_bounds__(256) void k_proj(
    const float* __restrict__ m, const float* __restrict__ mask,
    const float* __restrict__ gamma, const float* __restrict__ beta,
    const float* __restrict__ w1, const float* __restrict__ b1,
    const float* __restrict__ w2, const float* __restrict__ b2)
{
    __shared__ float As[128][36];
    __shared__ float Bs[32][72];
    int r0 = blockIdx.x*128;
    int t = threadIdx.x, wid = t>>5, lane = t&31;
    int g = lane>>2, tig = lane&3;
    int wm = (wid&1)*64, wn = (wid>>1)*16;
    float acc[4][2][4] = {};

    for (int k0=0;k0<CM_;k0+=32){
#pragma unroll
        for (int q=0;q<4;q++){
            int f = t + q*256;
            int row = f>>3; int k4 = (f&7)*4;
            float4 x  = *(const float4*)(m + (size_t)(r0+row)*CM_ + k0 + k4);
            float2 st = g_stats[r0+row];
            float4 gm = *(const float4*)(gamma + k0 + k4);
            float4 bt = *(const float4*)(beta  + k0 + k4);
            float4 v;
            v.x = (x.x-st.x)*st.y*gm.x + bt.x;
            v.y = (x.y-st.x)*st.y*gm.y + bt.y;
            v.z = (x.z-st.x)*st.y*gm.z + bt.z;
            v.w = (x.w-st.x)*st.y*gm.w + bt.w;
            *(float4*)&As[row][k4] = v;
        }
#pragma unroll
        for (int q=0;q<2;q++){
            int f = t + q*256;
            int k_l = f>>4; int h4 = (f&15)*4;
            float4 w;
            if (h4 < 32) w = *(const float4*)(w1 + (size_t)(k0+k_l)*CH_ + h4);
            else         w = *(const float4*)(w2 + (size_t)(k0+k_l)*CH_ + (h4-32));
            *(float4*)&Bs[k_l][h4] = w;
        }
        __syncthreads();
#pragma unroll
        for (int kk=0;kk<32;kk+=8){
            uint32_t af[4][4], bfr[2][2];
#pragma unroll
            for (int mi=0;mi<4;mi++){
                int mb = wm + mi*16;
                af[mi][0]=f2tf(As[mb+g  ][kk+tig  ]);
                af[mi][1]=f2tf(As[mb+g+8][kk+tig  ]);
                af[mi][2]=f2tf(As[mb+g  ][kk+tig+4]);
                af[mi][3]=f2tf(As[mb+g+8][kk+tig+4]);
            }
#pragma unroll
            for (int ni=0;ni<2;ni++){
                int nb = wn + ni*8;
                bfr[ni][0]=f2tf(Bs[kk+tig  ][nb+g]);
                bfr[ni][1]=f2tf(Bs[kk+tig+4][nb+g]);
            }
#pragma unroll
            for (int mi=0;mi<4;mi++)
#pragma unroll
                for (int ni=0;ni<2;ni++)
                    mma8(acc[mi][ni], af[mi], bfr[ni], acc[mi][ni]);
        }
        __syncthreads();
    }
#pragma unroll
    for (int mi=0;mi<4;mi++){
#pragma unroll
        for (int ni=0;ni<2;ni++){
            int h0 = wn + ni*8 + tig*2;
#pragma unroll
            for (int half=0; half<2; half++){
                int r = r0 + wm + mi*16 + g + half*8;
                int s_ = r / N_;
                int n_ = r - s_*N_;
                float mv = mask[(size_t)s_*N_ + n_];
#pragma unroll
                for (int e=0;e<2;e++){
                    int h = h0 + e;
                    float v = acc[mi][ni][half*2+e];
                    if (h < CH_) g_a2[(size_t)s_*P_ + n_*CH_ + h]       = (v + __ldg(&b1[h]))*mv;
                    else         g_b2[(size_t)s_*P_ + n_*CH_ + (h-CH_)] = (v + __ldg(&b2[h-CH_]))*mv;
                }
            }
        }
    }
}

// ---------------------------------------------------------------------------
// K_tr: transpose a2/b2 [S][P] fp32 -> [P][S] fp16
// ---------------------------------------------------------------------------
__global__ void k_tr(){
    __shared__ float tl[32][33];
    const float* src = blockIdx.z ? g_b2 : g_a2;
    __half*      dst = blockIdx.z ? g_b2T : g_a2T;
    int x = blockIdx.x*32 + threadIdx.x;
    int y0 = blockIdx.y*32;
#pragma unroll
    for (int i=0;i<4;i++)
        tl[threadIdx.y + i*8][threadIdx.x] = src[(size_t)(y0+threadIdx.y+i*8)*P_ + x];
    __syncthreads();
#pragma unroll
    for (int i=0;i<4;i++)
        dst[(size_t)(blockIdx.x*32 + threadIdx.y + i*8)*S_ + y0 + threadIdx.x]
            = __float2half(tl[threadIdx.x][threadIdx.y + i*8]);
}

// ---------------------------------------------------------------------------
// K2: fp16 outer GEMM. C1[p,q] = sum_s a2T[p][s]*b2T[q][s].
// ---------------------------------------------------------------------------
#define OSTR 136
__global__ __launch_bounds__(256,2) void k_outer_h(){
    extern __shared__ __align__(16) __half sm[];
    __half* Ah = sm;               // 128 x OSTR
    __half* Bh = sm + 128*OSTR;    // 128 x OSTR
    int t = threadIdx.x, wid = t>>5, lane = t&31;
    int g = lane>>2, tig = lane&3;
    int p0 = blockIdx.x*128, q0 = blockIdx.y*128;
    int wm = (wid&1)*64, wn = (wid>>1)*32;

#pragma unroll
    for (int q=0;q<8;q++){
        int idx = t + q*256;
        int row = idx>>4, u = idx&15;
        *(uint4*)&Ah[row*OSTR + u*8] = *(const uint4*)(g_a2T + (size_t)(p0+row)*S_ + u*8);
        *(uint4*)&Bh[row*OSTR + u*8] = *(const uint4*)(g_b2T + (size_t)(q0+row)*S_ + u*8);
    }
    __syncthreads();

    uint32_t a_base = cvta_smem(Ah);
    uint32_t b_base = cvta_smem(Bh);
    float acc[4][4][4] = {};
    int lrow = lane & 15, lcol = (lane>>4)*8;

#pragma unroll
    for (int kk=0;kk<8;kk++){
        int k0 = kk*16;
        uint32_t af[4][4], bf[4][2];
#pragma unroll
        for (int mi=0;mi<4;mi++){
            uint32_t addr = a_base + (uint32_t)(((wm + mi*16 + lrow)*OSTR + k0 + lcol)*2);
            ldmx4(af[mi][0], af[mi][1], af[mi][2], af[mi][3], addr);
        }
#pragma unroll
        for (int np=0;np<2;np++){
            uint32_t addr = b_base + (uint32_t)(((wn + np*16 + lrow)*OSTR + k0 + lcol)*2);
            uint32_t r0,r1,r2,r3;
            ldmx4(r0,r1,r2,r3,addr);
            bf[np*2  ][0]=r0; bf[np*2  ][1]=r2;
            bf[np*2+1][0]=r1; bf[np*2+1][1]=r3;
        }
#pragma unroll
        for (int mi=0;mi<4;mi++)
#pragma unroll
            for (int ni=0;ni<4;ni++)
                hmma16(acc[mi][ni], af[mi], bf[ni]);
    }
    __syncthreads();

    __half* Cs = Ah;
#pragma unroll
    for (int mi=0;mi<4;mi++)
#pragma unroll
        for (int ni=0;ni<4;ni++){
            int col = wn + ni*8 + tig*2;
#pragma unroll
            for (int half=0; half<2; half++){
                int row = wm + mi*16 + g + half*8;
                __half2 h = __floats2half2_rn(acc[mi][ni][half*2+0], acc[mi][ni][half*2+1]);
                *(__half2*)&Cs[row*OSTR + col] = h;
            }
        }
    __syncthreads();
#pragma unroll
    for (int q=0;q<8;q++){
        int idx = t + q*256;
        int row = idx>>4, u = idx&15;
        __stcs((uint4*)(g_C1h + (size_t)(p0+row)*P_ + q0 + u*8), *(uint4*)&Cs[row*OSTR + u*8]);
    }
}

// ---------------------------------------------------------------------------
// K3 v2: ldmatrix + K=64 stages (2 c's per stage), double-buffered.
//        out[(i,j),z] = (sum_{c,d} C1[i*32+c,(j0+j)*32+d]*w16T[c][z][d] + b)/norm
// ---------------------------------------------------------------------------
#define KSTR 72   // smem row stride in halves (64 + 8): 144B rows, bank-clean
__global__ __launch_bounds__(256,2) void k_out16(const float* __restrict__ bout,
                                                 float* __restrict__ out)
{
    extern __shared__ __align__(16) __half sm3[];
    __half* As = sm3;                 // [2][128*KSTR]
    __half* Ws = sm3 + 2*128*KSTR;    // [2][128*KSTR]
    int i  = blockIdx.y;
    int j0 = blockIdx.x*128;
    int t = threadIdx.x, wid = t>>5, lane = t&31;
    int g = lane>>2, tig = lane&3;
    int lrow = lane & 15, lcol = (lane>>4)*8;
    int wm = (wid&1)*64, wn = (wid>>1)*32;
    float acc[4][4][4] = {};

    uint32_t a_base = cvta_smem(As);
    uint32_t w_base = cvta_smem(Ws);

    uint4 ra[4], rw[4];
    // prologue: load stage 0 (c = 0,1)
#pragma unroll
    for (int cp=0;cp<2;cp++){
        const uint4* asrc = (const uint4*)(g_C1h + (size_t)(i*CH_+cp)*P_ + (size_t)j0*CH_);
        const uint4* wsrc = (const uint4*)(g_w16T + (size_t)cp*4096);
#pragma unroll
        for (int q=0;q<2;q++){
            int idx = t + q*256;
            ra[cp*2+q] = __ldcs(asrc + idx);
            rw[cp*2+q] = wsrc[idx];
        }
    }
#pragma unroll
    for (int cp=0;cp<2;cp++)
#pragma unroll
        for (int q=0;q<2;q++){
            int idx = t + q*256;          // 0..511
            int r_ = idx>>2, du = idx&3;
            *(uint4*)&As[r_*KSTR + cp*32 + du*8] = ra[cp*2+q];
            *(uint4*)&Ws[r_*KSTR + cp*32 + du*8] = rw[cp*2+q];
        }
    __syncthreads();

    for (int s=0;s<16;s++){
        int b = s&1;
        if (s<15){
            int c0 = (s+1)*2;
#pragma unroll
            for (int cp=0;cp<2;cp++){
                const uint4* asrc = (const uint4*)(g_C1h + (size_t)(i*CH_+c0+cp)*P_ + (size_t)j0*CH_);
                const uint4* wsrc = (const uint4*)(g_w16T + (size_t)(c0+cp)*4096);
#pragma unroll
                for (int q=0;q<2;q++){
                    int idx = t + q*256;
                    ra[cp*2+q] = __ldcs(asrc + idx);
                    rw[cp*2+q] = wsrc[idx];
                }
            }
        }
        uint32_t ab = a_base + (uint32_t)(b*128*KSTR*2);
        uint32_t wb = w_base + (uint32_t)(b*128*KSTR*2);
#pragma unroll
        for (int kk=0;kk<4;kk++){
            int k0 = kk*16;
            uint32_t af[4][4], bf[4][2];
#pragma unroll
            for (int mi=0;mi<4;mi++){
                uint32_t addr = ab + (uint32_t)(((wm + mi*16 + lrow)*KSTR + k0 + lcol)*2);
                ldmx4(af[mi][0], af[mi][1], af[mi][2], af[mi][3], addr);
            }
#pragma unroll
            for (int np=0;np<2;np++){
                uint32_t addr = wb + (uint32_t)(((wn + np*16 + lrow)*KSTR + k0 + lcol)*2);
                uint32_t r0,r1,r2,r3;
                ldmx4(r0,r1,r2,r3,addr);
                bf[np*2  ][0]=r0; bf[np*2  ][1]=r2;
                bf[np*2+1][0]=r1; bf[np*2+1][1]=r3;
            }
#pragma unroll
            for (int mi=0;mi<4;mi++)
#pragma unroll
                for (int ni=0;ni<4;ni++)
                    hmma16(acc[mi][ni], af[mi], bf[ni]);
        }
        __syncthreads();
        if (s<15){
            __half* Ad = As + (b^1)*128*KSTR;
            __half* Wd = Ws + (b^1)*128*KSTR;
#pragma unroll
            for (int cp=0;cp<2;cp++)
#pragma unroll
                for (int q=0;q<2;q++){
                    int idx = t + q*256;
                    int r_ = idx>>2, du = idx&3;
                    *(uint4*)&Ad[r_*KSTR + cp*32 + du*8] = ra[cp*2+q];
                    *(uint4*)&Wd[r_*KSTR + cp*32 + du*8] = rw[cp*2+q];
                }
            __syncthreads();
        }
    }

#pragma unroll
    for (int mi=0;mi<4;mi++){
#pragma unroll
        for (int ni=0;ni<4;ni++){
            int z = wn + ni*8 + tig*2;
            float bo0 = __ldg(&bout[z]), bo1 = __ldg(&bout[z+1]);
#pragma unroll
            for (int half=0; half<2; half++){
                int jl = wm + mi*16 + g + half*8;
                float inv = 1.f / g_norm[i*N_ + j0 + jl];
                float2 v = make_float2((acc[mi][ni][half*2+0] + bo0)*inv,
                                       (acc[mi][ni][half*2+1] + bo1)*inv);
                *(float2*)&out[((size_t)(i*N_ + j0 + jl))*CZ_ + z] = v;
            }
        }
    }
}

// ---------------------------------------------------------------------------
extern "C" void kernel_launch(void* const* d_in, const int* in_sizes, int n_in,
                              void* d_out, int out_size)
{
    const float* m     = (const float*)d_in[0];
    const float* mask  = (const float*)d_in[1];
    const float* gamma = (const float*)d_in[2];
    const float* beta  = (const float*)d_in[3];
    const float* w1    = (const float*)d_in[4];
    const float* b1    = (const float*)d_in[5];
    const float* w2    = (const float*)d_in[6];
    const float* b2    = (const float*)d_in[7];
    const float* w_out = (const float*)d_in[8];
    const float* b_out = (const float*)d_in[9];
    float* out = (float*)d_out;

    const int osmem = 2*128*OSTR*sizeof(__half);          // 69632
    const int o3smem = 4*128*KSTR*sizeof(__half);         // 73728
    cudaFuncSetAttribute(k_outer_h, cudaFuncAttributeMaxDynamicSharedMemorySize, osmem);
    cudaFuncSetAttribute(k_out16,  cudaFuncAttributeMaxDynamicSharedMemorySize, o3smem);

    k_stats<<<R_/8, 256>>>(m);
    k_norm<<<N_, N_>>>(mask);
    k_cvtw<<<(32*128*32)/256, 256>>>(w_out);
    k_proj<<<R_/128, 256>>>(m, mask, gamma, beta, w1, b1, w2, b2);
    dim3 gt(P_/32, S_/32, 2);
    k_tr<<<gt, dim3(32,8)>>>();
    dim3 g2(P_/128, P_/128);
    k_outer_h<<<g2, 256, osmem>>>();
    dim3 g3(N_/128, N_);
    k_out16<<<g3, 256, o3smem>>>(b_out, out);
}

// round 6
// speedup vs baseline: 2.0339x; 1.0439x over previous
#include <cuda_runtime.h>
#include <cuda_fp16.h>
#include <cstdint>

#define S_   128
#define N_   384
#define CM_  256
#define CH_  32
#define CZ_  128
#define P_   (N_*CH_)       // 12288
#define R_   (S_*N_)        // 49152

// Scratch (device globals)
__device__ __align__(128) float  g_a2 [S_*P_];           // [s][p] fp32
__device__ __align__(128) float  g_b2 [S_*P_];
__device__ __align__(128) __half g_a2T[(size_t)P_*S_];   // [p][s] fp16
__device__ __align__(128) __half g_b2T[(size_t)P_*S_];
__device__ __align__(128) __half g_w16T[32*128*32];      // [c][z][d] fp16
__device__ __align__(16)  float2 g_stats[R_];
__device__ __align__(16)  float  g_norm[N_*N_];

// ---------------- helpers ----------------
__device__ __forceinline__ uint32_t f2tf(float f){
    uint32_t u; asm("cvt.rna.tf32.f32 %0, %1;" : "=r"(u) : "f"(f)); return u;
}
__device__ __forceinline__ uint32_t cvta_smem(const void* p){
    uint32_t a; asm("{ .reg .u64 t; cvta.to.shared.u64 t, %1; cvt.u32.u64 %0, t; }" : "=r"(a) : "l"(p)); return a;
}
__device__ __forceinline__ void ldmx4(uint32_t& r0, uint32_t& r1, uint32_t& r2, uint32_t& r3, uint32_t addr){
    asm volatile("ldmatrix.sync.aligned.m8n8.x4.shared.b16 {%0,%1,%2,%3}, [%4];"
        : "=r"(r0), "=r"(r1), "=r"(r2), "=r"(r3) : "r"(addr));
}
__device__ __forceinline__ void mma8(float d[4], const uint32_t a[4], const uint32_t b[2], const float c[4]){
    asm volatile(
      "mma.sync.aligned.m16n8k8.row.col.f32.tf32.tf32.f32 "
      "{%0,%1,%2,%3},{%4,%5,%6,%7},{%8,%9},{%10,%11,%12,%13};\n"
      : "=f"(d[0]),"=f"(d[1]),"=f"(d[2]),"=f"(d[3])
      : "r"(a[0]),"r"(a[1]),"r"(a[2]),"r"(a[3]),
        "r"(b[0]),"r"(b[1]),
        "f"(c[0]),"f"(c[1]),"f"(c[2]),"f"(c[3]));
}
__device__ __forceinline__ void hmma16(float d[4], const uint32_t a[4], const uint32_t b[2]){
    asm volatile(
      "mma.sync.aligned.m16n8k16.row.col.f32.f16.f16.f32 "
      "{%0,%1,%2,%3},{%4,%5,%6,%7},{%8,%9},{%0,%1,%2,%3};\n"
      : "+f"(d[0]),"+f"(d[1]),"+f"(d[2]),"+f"(d[3])
      : "r"(a[0]),"r"(a[1]),"r"(a[2]),"r"(a[3]),
        "r"(b[0]),"r"(b[1]));
}

// ---------------------------------------------------------------------------
// K1a: per-row LayerNorm statistics
// ---------------------------------------------------------------------------
__global__ void k_stats(const float* __restrict__ m){
    int r = blockIdx.x*8 + (threadIdx.x>>5);
    int lane = threadIdx.x & 31;
    const float* row = m + (size_t)r*CM_;
    float s=0.f, s2=0.f;
#pragma unroll
    for (int j=0;j<8;j++){ float x = row[j*32+lane]; s += x; s2 += x*x; }
#pragma unroll
    for (int o=16;o;o>>=1){ s += __shfl_xor_sync(~0u,s,o); s2 += __shfl_xor_sync(~0u,s2,o); }
    if (lane==0){
        float mu = s*(1.f/CM_);
        float var = s2*(1.f/CM_) - mu*mu;
        g_stats[r] = make_float2(mu, rsqrtf(var + 1e-5f));
    }
}

// ---------------------------------------------------------------------------
// K0: norm[i,j]
// ---------------------------------------------------------------------------
__global__ void k_norm(const float* __restrict__ mask){
    __shared__ float mi[S_];
    int i = blockIdx.x, j = threadIdx.x;
    if (j < S_) mi[j] = mask[(size_t)j*N_ + i];
    __syncthreads();
    float acc = 0.f;
#pragma unroll 4
    for (int s=0;s<S_;s++) acc += mi[s]*mask[(size_t)s*N_ + j];
    g_norm[i*N_ + j] = acc + 1e-3f;
}

// ---------------------------------------------------------------------------
// K_w: w_out -> fp16, transposed per c-chunk: g_w16T[c][z][d]
// ---------------------------------------------------------------------------
__global__ void k_cvtw(const float* __restrict__ w_out){
    int o = blockIdx.x*256 + threadIdx.x;        // [c][z][d]
    int d = o & 31, z = (o>>5) & 127, c = o>>12;
    g_w16T[o] = __float2half(w_out[(size_t)(c*32+d)*CZ_ + z]);
}

// ---------------------------------------------------------------------------
// K1b: fused LN + dual projection (legacy tf32 mma)
// ---------------------------------------------------------------------------
__global__ __launch_bounds__(256) void k_proj(
    const float* __restrict__ m, const float* __restrict__ mask,
    const float* __restrict__ gamma, const float* __restrict__ beta,
    const float* __restrict__ w1, const float* __restrict__ b1,
    const float* __restrict__ w2, const float* __restrict__ b2)
{
    __shared__ float As[128][36];
    __shared__ float Bs[32][72];
    int r0 = blockIdx.x*128;
    int t = threadIdx.x, wid = t>>5, lane = t&31;
    int g = lane>>2, tig = lane&3;
    int wm = (wid&1)*64, wn = (wid>>1)*16;
    float acc[4][2][4] = {};

    for (int k0=0;k0<CM_;k0+=32){
#pragma unroll
        for (int q=0;q<4;q++){
            int f = t + q*256;
            int row = f>>3; int k4 = (f&7)*4;
            float4 x  = *(const float4*)(m + (size_t)(r0+row)*CM_ + k0 + k4);
            float2 st = g_stats[r0+row];
            float4 gm = *(const float4*)(gamma + k0 + k4);
            float4 bt = *(const float4*)(beta  + k0 + k4);
            float4 v;
            v.x = (x.x-st.x)*st.y*gm.x + bt.x;
            v.y = (x.y-st.x)*st.y*gm.y + bt.y;
            v.z = (x.z-st.x)*st.y*gm.z + bt.z;
            v.w = (x.w-st.x)*st.y*gm.w + bt.w;
            *(float4*)&As[row][k4] = v;
        }
#pragma unroll
        for (int q=0;q<2;q++){
            int f = t + q*256;
            int k_l = f>>4; int h4 = (f&15)*4;
            float4 w;
            if (h4 < 32) w = *(const float4*)(w1 + (size_t)(k0+k_l)*CH_ + h4);
            else         w = *(const float4*)(w2 + (size_t)(k0+k_l)*CH_ + (h4-32));
            *(float4*)&Bs[k_l][h4] = w;
        }
        __syncthreads();
#pragma unroll
        for (int kk=0;kk<32;kk+=8){
            uint32_t af[4][4], bfr[2][2];
#pragma unroll
            for (int mi=0;mi<4;mi++){
                int mb = wm + mi*16;
                af[mi][0]=f2tf(As[mb+g  ][kk+tig  ]);
                af[mi][1]=f2tf(As[mb+g+8][kk+tig  ]);
                af[mi][2]=f2tf(As[mb+g  ][kk+tig+4]);
                af[mi][3]=f2tf(As[mb+g+8][kk+tig+4]);
            }
#pragma unroll
            for (int ni=0;ni<2;ni++){
                int nb = wn + ni*8;
                bfr[ni][0]=f2tf(Bs[kk+tig  ][nb+g]);
                bfr[ni][1]=f2tf(Bs[kk+tig+4][nb+g]);
            }
#pragma unroll
            for (int mi=0;mi<4;mi++)
#pragma unroll
                for (int ni=0;ni<2;ni++)
                    mma8(acc[mi][ni], af[mi], bfr[ni], acc[mi][ni]);
        }
        __syncthreads();
    }
#pragma unroll
    for (int mi=0;mi<4;mi++){
#pragma unroll
        for (int ni=0;ni<2;ni++){
            int h0 = wn + ni*8 + tig*2;
#pragma unroll
            for (int half=0; half<2; half++){
                int r = r0 + wm + mi*16 + g + half*8;
                int s_ = r / N_;
                int n_ = r - s_*N_;
                float mv = mask[(size_t)s_*N_ + n_];
#pragma unroll
                for (int e=0;e<2;e++){
                    int h = h0 + e;
                    float v = acc[mi][ni][half*2+e];
                    if (h < CH_) g_a2[(size_t)s_*P_ + n_*CH_ + h]       = (v + __ldg(&b1[h]))*mv;
                    else         g_b2[(size_t)s_*P_ + n_*CH_ + (h-CH_)] = (v + __ldg(&b2[h-CH_]))*mv;
                }
            }
        }
    }
}

// ---------------------------------------------------------------------------
// K_tr: transpose a2/b2 [S][P] fp32 -> [P][S] fp16
// ---------------------------------------------------------------------------
__global__ void k_tr(){
    __shared__ float tl[32][33];
    const float* src = blockIdx.z ? g_b2 : g_a2;
    __half*      dst = blockIdx.z ? g_b2T : g_a2T;
    int x = blockIdx.x*32 + threadIdx.x;
    int y0 = blockIdx.y*32;
#pragma unroll
    for (int i=0;i<4;i++)
        tl[threadIdx.y + i*8][threadIdx.x] = src[(size_t)(y0+threadIdx.y+i*8)*P_ + x];
    __syncthreads();
#pragma unroll
    for (int i=0;i<4;i++)
        dst[(size_t)(blockIdx.x*32 + threadIdx.y + i*8)*S_ + y0 + threadIdx.x]
            = __float2half(tl[threadIdx.x][threadIdx.y + i*8]);
}

// ---------------------------------------------------------------------------
// K_fused: K2+K3 fused. CTA = (16 i, 8 j). No C1 materialization.
//   Bs resident: 256 q-rows x 128 s (q = (j0+j)*32+d)
//   Loop 16 c-chunks (2 c's each):
//     GEMM1: Cc[32 rows=(i,cp)][256 q] = A_chunk @ Bs^T (fp16 mma, K=128)
//     GEMM2: acc2[128 pairs][128 z] += Cc (as [pair][(cp,d)]) @ W chunk
// ---------------------------------------------------------------------------
#define BSTR 136   // Bs/As row stride (halves)
#define WSTR 72    // Ws row stride
#define CSTR 328   // Cc row stride (j-substride 40)
#define BS_OFF 0
#define AS_OFF (256*BSTR)                 // 34816
#define WS_OFF (AS_OFF + 2*32*BSTR)       // +8704
#define CC_OFF (WS_OFF + 2*128*WSTR)      // +18432
#define SMH_TOT (CC_OFF + 2*32*CSTR)      // +20992 = 82944 halves = 165888 B

__global__ __launch_bounds__(256,1) void k_fused(const float* __restrict__ bout,
                                                 float* __restrict__ out)
{
    extern __shared__ __align__(16) __half sf[];
    __half* Bs = sf + BS_OFF;
    __half* As = sf + AS_OFF;
    __half* Ws = sf + WS_OFF;
    __half* Cc = sf + CC_OFF;

    const int t = threadIdx.x, wid = t>>5, lane = t&31;
    const int g = lane>>2, tig = lane&3;
    const int lrow = lane&15, lcol = (lane>>4)*8;
    const int j0 = blockIdx.x*8, i0 = blockIdx.y*16;

    // ---- load resident B slice: 256 rows x 128 halves ----
#pragma unroll
    for (int q=0;q<16;q++){
        int idx = t + q*256;
        int row = idx>>4, u = idx&15;
        *(uint4*)&Bs[row*BSTR + u*8] = *(const uint4*)(g_b2T + (size_t)(j0*32+row)*S_ + u*8);
    }

    uint4 ra[2], rw[4];
    // ---- prologue: load chunk 0 A/W ----
    {
        const int c0 = 0;
#pragma unroll
        for (int q=0;q<2;q++){
            int idx = t + q*256;
            int row = idx>>4, u = idx&15;
            int p = (i0 + (row>>1))*CH_ + c0 + (row&1);
            ra[q] = *(const uint4*)(g_a2T + (size_t)p*S_ + u*8);
        }
#pragma unroll
        for (int q=0;q<4;q++){
            int idx = t + q*256;
            int cp = idx>>9, z = (idx>>2)&127, du = idx&3;
            rw[q] = *(const uint4*)(g_w16T + (size_t)(c0+cp)*4096 + z*32 + du*8);
        }
#pragma unroll
        for (int q=0;q<2;q++){
            int idx = t + q*256;
            int row = idx>>4, u = idx&15;
            *(uint4*)&As[row*BSTR + u*8] = ra[q];
        }
#pragma unroll
        for (int q=0;q<4;q++){
            int idx = t + q*256;
            int cp = idx>>9, z = (idx>>2)&127, du = idx&3;
            *(uint4*)&Ws[z*WSTR + cp*32 + du*8] = rw[q];
        }
    }
    __syncthreads();

    const uint32_t bs_b = cvta_smem(Bs);
    const uint32_t as_b = cvta_smem(As);
    const uint32_t ws_b = cvta_smem(Ws);
    const uint32_t cc_b = cvta_smem(Cc);
    const int wm1 = (wid&1)*16;        // GEMM1 m-offset
    const int wn1 = (wid>>1)*64;       // GEMM1 n-offset

    float acc2[16][4];
#pragma unroll
    for (int a=0;a<16;a++){ acc2[a][0]=0.f; acc2[a][1]=0.f; acc2[a][2]=0.f; acc2[a][3]=0.f; }

    // ---- GEMM1 for chunk 0 -> Cc buffer 0 ----
    {
        float acc1[8][4];
#pragma unroll
        for (int a=0;a<8;a++){ acc1[a][0]=0.f; acc1[a][1]=0.f; acc1[a][2]=0.f; acc1[a][3]=0.f; }
        uint32_t ab = as_b;
#pragma unroll
        for (int kk=0;kk<8;kk++){
            int k0 = kk*16;
            uint32_t af[4], bf[8][2];
            ldmx4(af[0],af[1],af[2],af[3], ab + (uint32_t)(((wm1+lrow)*BSTR + k0 + lcol)*2));
#pragma unroll
            for (int np=0;np<4;np++){
                uint32_t r0,r1,r2,r3;
                ldmx4(r0,r1,r2,r3, bs_b + (uint32_t)(((wn1+np*16+lrow)*BSTR + k0 + lcol)*2));
                bf[np*2  ][0]=r0; bf[np*2  ][1]=r2;
                bf[np*2+1][0]=r1; bf[np*2+1][1]=r3;
            }
#pragma unroll
            for (int ni=0;ni<8;ni++) hmma16(acc1[ni], af, bf[ni]);
        }
        __half* Cb = Cc;
#pragma unroll
        for (int ni=0;ni<8;ni++){
            int q = wn1 + ni*8 + tig*2;
            int col = (q>>5)*40 + (q&31);
#pragma unroll
            for (int half=0; half<2; half++){
                int mr = wm1 + g + half*8;
                *(__half2*)&Cb[mr*CSTR + col] =
                    __floats2half2_rn(acc1[ni][half*2+0], acc1[ni][half*2+1]);
            }
        }
    }

    // ---- main loop over 16 c-chunks ----
    for (int k=0;k<16;k++){
        int bc = k&1;
        if (k<15){
            int c0 = (k+1)*2;
#pragma unroll
            for (int q=0;q<2;q++){
                int idx = t + q*256;
                int row = idx>>4, u = idx&15;
                int p = (i0 + (row>>1))*CH_ + c0 + (row&1);
                ra[q] = *(const uint4*)(g_a2T + (size_t)p*S_ + u*8);
            }
#pragma unroll
            for (int q=0;q<4;q++){
                int idx = t + q*256;
                int cp = idx>>9, z = (idx>>2)&127, du = idx&3;
                rw[q] = *(const uint4*)(g_w16T + (size_t)(c0+cp)*4096 + z*32 + du*8);
            }
        }
        __syncthreads();   // Cc(k), Ws(k) visible

        // ---- GEMM2 chunk k: 4 k-steps of k16 over (cp,dh) ----
        {
            uint32_t cb = cc_b + (uint32_t)(bc*32*CSTR*2);
            uint32_t wb = ws_b + (uint32_t)(bc*128*WSTR*2);
#pragma unroll
            for (int kk=0;kk<4;kk++){
                int cp = kk>>1, dh = (kk&1)*16;
                uint32_t af[4], bf[16][2];
                ldmx4(af[0],af[1],af[2],af[3],
                      cb + (uint32_t)((((wid*2 + (lrow>>3))*2 + cp)*CSTR + (lrow&7)*40 + dh + lcol)*2));
#pragma unroll
                for (int np=0;np<8;np++){
                    uint32_t r0,r1,r2,r3;
                    ldmx4(r0,r1,r2,r3, wb + (uint32_t)(((np*16+lrow)*WSTR + cp*32 + dh + lcol)*2));
                    bf[np*2  ][0]=r0; bf[np*2  ][1]=r2;
                    bf[np*2+1][0]=r1; bf[np*2+1][1]=r3;
                }
#pragma unroll
                for (int ni=0;ni<16;ni++) hmma16(acc2[ni], af, bf[ni]);
            }
        }

        if (k<15){
            // store A/W (k+1) into buffers bc^1
            __half* Ab = As + (bc^1)*32*BSTR;
            __half* Wb = Ws + (bc^1)*128*WSTR;
#pragma unroll
            for (int q=0;q<2;q++){
                int idx = t + q*256;
                int row = idx>>4, u = idx&15;
                *(uint4*)&Ab[row*BSTR + u*8] = ra[q];
            }
#pragma unroll
            for (int q=0;q<4;q++){
                int idx = t + q*256;
                int cp = idx>>9, z = (idx>>2)&127, du = idx&3;
                *(uint4*)&Wb[z*WSTR + cp*32 + du*8] = rw[q];
            }
            __syncthreads();  // A/W(k+1) visible; Cc[bc^1] free to overwrite

            // ---- GEMM1 chunk k+1 -> Cc[bc^1] ----
            float acc1[8][4];
#pragma unroll
            for (int a=0;a<8;a++){ acc1[a][0]=0.f; acc1[a][1]=0.f; acc1[a][2]=0.f; acc1[a][3]=0.f; }
            uint32_t ab = as_b + (uint32_t)((bc^1)*32*BSTR*2);
#pragma unroll
            for (int kk=0;kk<8;kk++){
                int k0 = kk*16;
                uint32_t af[4], bf[8][2];
                ldmx4(af[0],af[1],af[2],af[3], ab + (uint32_t)(((wm1+lrow)*BSTR + k0 + lcol)*2));
#pragma unroll
                for (int np=0;np<4;np++){
                    uint32_t r0,r1,r2,r3;
                    ldmx4(r0,r1,r2,r3, bs_b + (uint32_t)(((wn1+np*16+lrow)*BSTR + k0 + lcol)*2));
                    bf[np*2  ][0]=r0; bf[np*2  ][1]=r2;
                    bf[np*2+1][0]=r1; bf[np*2+1][1]=r3;
                }
#pragma unroll
                for (int ni=0;ni<8;ni++) hmma16(acc1[ni], af, bf[ni]);
            }
            __half* Cb = Cc + (bc^1)*32*CSTR;
#pragma unroll
            for (int ni=0;ni<8;ni++){
                int q = wn1 + ni*8 + tig*2;
                int col = (q>>5)*40 + (q&31);
#pragma unroll
                for (int half=0; half<2; half++){
                    int mr = wm1 + g + half*8;
                    *(__half2*)&Cb[mr*CSTR + col] =
                        __floats2half2_rn(acc1[ni][half*2+0], acc1[ni][half*2+1]);
                }
            }
        }
    }

    // ---- epilogue: bias + norm, write out ----
#pragma unroll
    for (int ni=0;ni<16;ni++){
        int z = ni*8 + tig*2;
        float bo0 = __ldg(&bout[z]), bo1 = __ldg(&bout[z+1]);
#pragma unroll
        for (int half=0; half<2; half++){
            int i = i0 + wid*2 + half;
            int j = j0 + g;
            float inv = 1.f / g_norm[i*N_ + j];
            float2 v = make_float2((acc2[ni][half*2+0] + bo0)*inv,
                                   (acc2[ni][half*2+1] + bo1)*inv);
            *(float2*)&out[((size_t)i*N_ + j)*CZ_ + z] = v;
        }
    }
}

// ---------------------------------------------------------------------------
extern "C" void kernel_launch(void* const* d_in, const int* in_sizes, int n_in,
                              void* d_out, int out_size)
{
    const float* m     = (const float*)d_in[0];
    const float* mask  = (const float*)d_in[1];
    const float* gamma = (const float*)d_in[2];
    const float* beta  = (const float*)d_in[3];
    const float* w1    = (const float*)d_in[4];
    const float* b1    = (const float*)d_in[5];
    const float* w2    = (const float*)d_in[6];
    const float* b2    = (const float*)d_in[7];
    const float* w_out = (const float*)d_in[8];
    const float* b_out = (const float*)d_in[9];
    float* out = (float*)d_out;

    const int fsmem = SMH_TOT*2;  // 165888 bytes
    cudaFuncSetAttribute(k_fused, cudaFuncAttributeMaxDynamicSharedMemorySize, fsmem);

    k_stats<<<R_/8, 256>>>(m);
    k_norm<<<N_, N_>>>(mask);
    k_cvtw<<<(32*128*32)/256, 256>>>(w_out);
    k_proj<<<R_/128, 256>>>(m, mask, gamma, beta, w1, b1, w2, b2);
    dim3 gt(P_/32, S_/32, 2);
    k_tr<<<gt, dim3(32,8)>>>();
    dim3 gf(N_/8, N_/16);
    k_fused<<<gf, 256, fsmem>>>(b_out, out);
}